// round 10
// baseline (speedup 1.0000x reference)
#include <cuda_runtime.h>
#include <cstddef>

// Problem constants (fixed by reference)
#define N_KC   200
#define N_MBON 20
#define N_FBN  60
#define N_DAN  20
#define N_REC  100
#define T_TOT  61
#define T_STEPS 60
#define KPT    7          // k = lane + 32*i, valid k < 200
#define NTHREADS 320
#define WM_CHUNK 36       // Wm cols per thread-group (9 float4s, zero-padded)
#define WM_Q     9

// smem layout (floats)
#define OFF_RK   0        // 12200 : r_kc slab [k*61 + t]
#define OFF_R    12200    // 108   : current r, zero-padded to 108 (float4 reads)
#define OFF_IB   12308    // 80    : I_kc partials (4 lanes x 20 rows)
#define OFF_WRP  12388    // 300   : Wr partials
#define OFF_RBK  12688    // 400   : rbk double buffer (2 x 200)
#define OFF_BIAS 13088    // 100
#define OFF_WRO  13188    // 20
#define OFF_WEXT 13208    // 120
#define OFF_REXT 13328    // 122
#define SM_FLOATS 13450

__global__ __launch_bounds__(NTHREADS, 2)
void cond_rnn_kernel(const float* __restrict__ r_kc,
                     const float* __restrict__ r_ext,
                     const float* __restrict__ timev,
                     const float* __restrict__ W0,
                     const float* __restrict__ wt0,
                     const float* __restrict__ W_recur,
                     const float* __restrict__ W_ext,
                     const float* __restrict__ W_readout,
                     const float* __restrict__ bias,
                     float* __restrict__ out,
                     int B)
{
    extern __shared__ float sm[];
    float* s_rk   = sm + OFF_RK;
    float* s_r    = sm + OFF_R;
    float* s_Ib   = sm + OFF_IB;
    float* s_wrp  = sm + OFF_WRP;
    float* s_rbk  = sm + OFF_RBK;   // two buffers of 200
    float* s_bias = sm + OFF_BIAS;
    float* s_wro  = sm + OFF_WRO;
    float* s_wext = sm + OFF_WEXT;
    float* s_rext = sm + OFF_REXT;

    const int b    = blockIdx.x;
    const int tid  = threadIdx.x;
    const int w    = tid >> 5;     // warp id 0..9
    const int lane = tid & 31;

    const float dt = timev[1] - timev[0];
    const float cW = dt * (1.0f / 5.0f);  // dt / TAU_W
    const float cR = dt;                  // dt / TAU_R

    // output section offsets
    const size_t WF   = (size_t)T_TOT * B * N_REC;
    const size_t WTF  = WF + (size_t)B * (N_MBON * N_KC);
    const size_t RO   = WTF + (size_t)B * (N_MBON * N_KC);

    // ---- stage r_kc[b] slab into smem (coalesced float4) ----
    const float* rkb = r_kc + (size_t)b * (N_KC * T_TOT);
    {
        const float4* src = (const float4*)rkb;
        float4* dst = (float4*)s_rk;
        for (int i = tid; i < (N_KC * T_TOT) / 4; i += NTHREADS) dst[i] = src[i];
    }

    // ---- init small shared state ----
    if (tid < 100) {
        s_bias[tid] = bias[tid];
        float r0 = (tid < N_MBON) ? 0.0f : 0.1f;
        s_r[tid] = r0;
        out[(size_t)b * N_REC + tid] = r0;          // r_all[0]
    }
    if (tid >= 100 && tid < 108) s_r[tid] = 0.0f;   // zero pad for float4 Wr reads
    if (tid < 20)  s_wro[tid] = W_readout[tid];
    if (tid < 120) s_wext[tid] = W_ext[tid];
    if (tid < 200) s_rbk[tid] = rkb[tid * T_TOT];   // rbk0 into buffer 0
    if (tid < 122) s_rext[tid] = r_ext[(size_t)b * (2 * T_TOT) + tid];
    if (tid == 0)  out[RO + b] = 0.0f;              // readout0 (MBON r is 0)

    // ---- plastic weights W / wt in registers: warp w owns rows (w, w+10) ----
    const int m1 = w;
    const int m2 = w + 10;
    float Wa[KPT], Wb_[KPT], wta[KPT], wtb[KPT];
    {
        const float* Wg  = W0  + (size_t)b * (N_MBON * N_KC);
        const float* wtg = wt0 + (size_t)b * (N_MBON * N_KC);
        #pragma unroll
        for (int i = 0; i < KPT; i++) {
            int k = lane + 32 * i;
            bool ok = (k < N_KC);
            Wa[i]  = ok ? Wg [m1 * N_KC + k] : 0.0f;
            Wb_[i] = ok ? Wg [m2 * N_KC + k] : 0.0f;
            wta[i] = ok ? wtg[m1 * N_KC + k] : 0.0f;
            wtb[i] = ok ? wtg[m2 * N_KC + k] : 0.0f;
        }
    }

    // per-warp DAN / rbd state (register-resident, rows m1 and m2)
    float rdan1 = 0.1f, rdan2 = 0.1f;   // r_init DAN = 0.1
    float rbd1  = 0.1f, rbd2  = 0.1f;   // rbd0 = 0.1

    // ---- W_recur (masked -> Wm) in registers: thread-group (jj, i0) ----
    float wm[WM_CHUNK];
    const int jj = (tid < 300) ? (tid % 100) : 0;
    const int i0 = (tid < 300) ? (tid / 100) * WM_CHUNK : 0;
    #pragma unroll
    for (int c = 0; c < WM_CHUNK; c++) {
        int ia = i0 + c;
        float v = 0.0f;
        if (tid < 300 && ia < N_REC) {
            v = W_recur[jj * N_REC + ia];
            if (jj < N_MBON && ia >= N_REC - N_DAN) v = 0.0f;  // Wm mask
        }
        wm[c] = v;
    }

    __syncthreads();

    float* out_r = out + (size_t)B * N_REC + (size_t)b * N_REC;  // r_all[1]
    const size_t rstride = (size_t)B * N_REC;

    for (int t = 0; t < T_STEPS; t++) {
        const int cur = t & 1;
        const int nxt = cur ^ 1;

        // ================= P0 =================
        // rk into regs + I_kc row dots (2 independent chains)
        float rk[KPT];
        #pragma unroll
        for (int i = 0; i < KPT; i++) {
            int k = lane + 32 * i;
            rk[i] = (k < N_KC) ? s_rk[k * T_TOT + t] : 0.0f;
        }
        float p1 = 0.0f, p2 = 0.0f;
        #pragma unroll
        for (int i = 0; i < KPT; i++) {
            p1 = fmaf(Wa[i],  rk[i], p1);
            p2 = fmaf(Wb_[i], rk[i], p2);
        }
        // 3-level butterfly: lanes 0..3 hold partials over lanes == l mod 4
        #pragma unroll
        for (int o = 16; o >= 4; o >>= 1) {
            p1 += __shfl_xor_sync(0xFFFFFFFFu, p1, o);
            p2 += __shfl_xor_sync(0xFFFFFFFFu, p2, o);
        }
        if (lane < 4) {
            s_Ib[lane * 20 + m1] = p1;
            s_Ib[lane * 20 + m2] = p2;
        }

        // Wr partials: 9 float4 broadcast loads, 2 accumulator chains
        if (tid < 300) {
            const float4* rp = (const float4*)(s_r + i0);
            float a0 = 0.f, a1 = 0.f;
            #pragma unroll
            for (int c = 0; c < WM_Q; c++) {
                float4 rv = rp[c];
                a0 = fmaf(wm[4 * c],     rv.x, a0);
                a1 = fmaf(wm[4 * c + 1], rv.y, a1);
                a0 = fmaf(wm[4 * c + 2], rv.z, a0);
                a1 = fmaf(wm[4 * c + 3], rv.w, a1);
            }
            s_wrp[tid] = a0 + a1;
        }

        // rbk update: read buf[cur], write buf[nxt]
        if (tid < N_KC) {
            float rbk = s_rbk[cur * 200 + tid];
            float rkt = s_rk[tid * T_TOT + t];
            s_rbk[nxt * 200 + tid] = fmaf(rkt - rbk, cW, rbk);
        }

        // readout of r(t) (warp 9; s_r holds r(t) here)
        if (w == 9 && t > 0) {
            float v = (lane < N_MBON) ? s_r[lane] * s_wro[lane] : 0.0f;
            #pragma unroll
            for (int o = 16; o > 0; o >>= 1)
                v += __shfl_xor_sync(0xFFFFFFFFu, v, o);
            if (lane == 0) out[RO + (size_t)t * B + b] = v;
        }
        __syncthreads();

        // ========== P1 (threads 0..99) CONCURRENT WITH P2 (all warps) ==========

        // --- P1: full r update into s_r (for next step's Wr / readout) ---
        if (tid < N_REC) {
            float x = s_wrp[tid] + s_wrp[100 + tid] + s_wrp[200 + tid]
                    + s_bias[tid];
            if (tid < N_MBON) {
                x += (s_Ib[tid] + s_Ib[20 + tid]) + (s_Ib[40 + tid] + s_Ib[60 + tid]);
            } else if (tid < N_MBON + N_FBN) {
                int q = tid - N_MBON;
                float re0 = s_rext[t];
                float re1 = s_rext[T_TOT + t];
                x += fmaf(s_wext[2 * q], re0, s_wext[2 * q + 1] * re1);
            }
            float rold = s_r[tid];
            float rn = fmaf(fmaxf(x, 0.0f) - rold, cR, rold);
            s_r[tid] = rn;
            out_r[tid] = rn;
        }

        // --- P2: in-warp DAN update + plasticity (needs only s_wrp/s_bias/rbk) ---
        {
            // r_dan rows m1, m2 — identical arithmetic order to P1's DAN path
            int j1 = 80 + m1, j2 = 80 + m2;
            float x1 = s_wrp[j1] + s_wrp[100 + j1] + s_wrp[200 + j1] + s_bias[j1];
            float x2 = s_wrp[j2] + s_wrp[100 + j2] + s_wrp[200 + j2] + s_bias[j2];
            rdan1 = fmaf(fmaxf(x1, 0.0f) - rdan1, cR, rdan1);
            rdan2 = fmaf(fmaxf(x2, 0.0f) - rdan2, cR, rdan2);
            rbd1  = fmaf(rdan1 - rbd1, cW, rbd1);
            rbd2  = fmaf(rdan2 - rbd2, cW, rbd2);

            float rbd1d = rbd1 * dt,   rbd2d = rbd2 * dt;
            float rdn1d = -rdan1 * dt, rdn2d = -rdan2 * dt;
            const float* rbk_new = s_rbk + nxt * 200;
            #pragma unroll
            for (int i = 0; i < KPT; i++) {
                int k = lane + 32 * i;
                if (k < N_KC) {
                    float rbk = rbk_new[k];
                    wta[i] = fmaf(rbd1d, rk[i], wta[i]);
                    wta[i] = fmaf(rdn1d, rbk,   wta[i]);
                    Wa[i]  = fminf(fmaxf(fmaf(wta[i] - Wa[i], cW, Wa[i]), 0.0f), 0.05f);
                    wtb[i] = fmaf(rbd2d, rk[i], wtb[i]);
                    wtb[i] = fmaf(rdn2d, rbk,   wtb[i]);
                    Wb_[i] = fminf(fmaxf(fmaf(wtb[i] - Wb_[i], cW, Wb_[i]), 0.0f), 0.05f);
                }
            }
        }

        out_r += rstride;
        __syncthreads();   // protect s_r (next Wr/readout) + s_wrp/s_Ib/rbk reuse
    }

    // ---- tail: readout of r(60), final W / wt ----
    if (w == 9) {
        float v = (lane < N_MBON) ? s_r[lane] * s_wro[lane] : 0.0f;
        #pragma unroll
        for (int o = 16; o > 0; o >>= 1)
            v += __shfl_xor_sync(0xFFFFFFFFu, v, o);
        if (lane == 0) out[RO + (size_t)T_STEPS * B + b] = v;
    }
    {
        float* Wf  = out + WF  + (size_t)b * (N_MBON * N_KC);
        float* wtf = out + WTF + (size_t)b * (N_MBON * N_KC);
        #pragma unroll
        for (int i = 0; i < KPT; i++) {
            int k = lane + 32 * i;
            if (k < N_KC) {
                Wf [m1 * N_KC + k] = Wa[i];
                Wf [m2 * N_KC + k] = Wb_[i];
                wtf[m1 * N_KC + k] = wta[i];
                wtf[m2 * N_KC + k] = wtb[i];
            }
        }
    }
}

extern "C" void kernel_launch(void* const* d_in, const int* in_sizes, int n_in,
                              void* d_out, int out_size) {
    const float* r_kc      = (const float*)d_in[0];
    const float* r_ext     = (const float*)d_in[1];
    const float* timev     = (const float*)d_in[2];
    const float* W0        = (const float*)d_in[3];
    const float* wt0       = (const float*)d_in[4];
    const float* W_recur   = (const float*)d_in[5];
    const float* W_ext     = (const float*)d_in[6];
    const float* W_readout = (const float*)d_in[7];
    const float* bias      = (const float*)d_in[8];
    float* out = (float*)d_out;

    int B = in_sizes[0] / (N_KC * T_TOT);

    static bool attr_set = false;
    if (!attr_set) {
        cudaFuncSetAttribute(cond_rnn_kernel,
                             cudaFuncAttributeMaxDynamicSharedMemorySize,
                             SM_FLOATS * sizeof(float));
        attr_set = true;
    }

    cond_rnn_kernel<<<B, NTHREADS, SM_FLOATS * sizeof(float)>>>(
        r_kc, r_ext, timev, W0, wt0, W_recur, W_ext, W_readout, bias, out, B);
}

// round 11
// speedup vs baseline: 1.1303x; 1.1303x over previous
#include <cuda_runtime.h>
#include <cstddef>

typedef unsigned long long ull;

// Problem constants (fixed by reference)
#define N_KC   200
#define N_MBON 20
#define N_FBN  60
#define N_DAN  20
#define N_REC  100
#define T_TOT  61
#define T_STEPS 60
#define KPT    7          // k = lane + 32*i, valid k < 200
#define NTHREADS 320
#define WM_CHUNK 36       // Wm cols per thread-group (zero-padded)
#define WM_PAIRS 18
#define WM_Q     9

// smem layout (floats)
#define OFF_RK   0        // 12200 : r_kc slab [k*61 + t]
#define OFF_R    12200    // 108   : current r, zero-padded to 108 (16B reads)
#define OFF_IB   12308    // 80    : I_kc partials (4 lanes x 20 rows)
#define OFF_WRP  12388    // 300   : Wr partials
#define OFF_RBK  12688    // 400   : rbk double buffer (2 x 200)
#define OFF_RBD  13088    // 20
#define OFF_BIAS 13108    // 100
#define OFF_WRO  13208    // 20
#define OFF_WEXT 13228    // 120
#define OFF_REXT 13348    // 122
#define SM_FLOATS 13470

#define FMA2(d,a,b,c) asm("fma.rn.f32x2 %0, %1, %2, %3;" : "=l"(d) : "l"(a), "l"(b), "l"(c))

__device__ __forceinline__ ull pk2(float a, float b) {
    ull r;
    asm("mov.b64 %0, {%1, %2};" : "=l"(r)
        : "r"(__float_as_uint(a)), "r"(__float_as_uint(b)));
    return r;
}
__device__ __forceinline__ void upk2(ull v, float& a, float& b) {
    unsigned lo, hi;
    asm("mov.b64 {%0, %1}, %2;" : "=r"(lo), "=r"(hi) : "l"(v));
    a = __uint_as_float(lo); b = __uint_as_float(hi);
}

__global__ __launch_bounds__(NTHREADS, 2)
void cond_rnn_kernel(const float* __restrict__ r_kc,
                     const float* __restrict__ r_ext,
                     const float* __restrict__ timev,
                     const float* __restrict__ W0,
                     const float* __restrict__ wt0,
                     const float* __restrict__ W_recur,
                     const float* __restrict__ W_ext,
                     const float* __restrict__ W_readout,
                     const float* __restrict__ bias,
                     float* __restrict__ out,
                     int B)
{
    extern __shared__ float sm[];
    float* s_rk   = sm + OFF_RK;
    float* s_r    = sm + OFF_R;
    float* s_Ib   = sm + OFF_IB;
    float* s_wrp  = sm + OFF_WRP;
    float* s_rbk  = sm + OFF_RBK;   // two buffers of 200
    float* s_rbd  = sm + OFF_RBD;
    float* s_bias = sm + OFF_BIAS;
    float* s_wro  = sm + OFF_WRO;
    float* s_wext = sm + OFF_WEXT;
    float* s_rext = sm + OFF_REXT;

    const int b    = blockIdx.x;
    const int tid  = threadIdx.x;
    const int w    = tid >> 5;     // warp id 0..9
    const int lane = tid & 31;

    const float dt = timev[1] - timev[0];
    const float cW = dt * (1.0f / 5.0f);  // dt / TAU_W
    const float cR = dt;                  // dt / TAU_R

    // output section offsets
    const size_t WF   = (size_t)T_TOT * B * N_REC;
    const size_t WTF  = WF + (size_t)B * (N_MBON * N_KC);
    const size_t RO   = WTF + (size_t)B * (N_MBON * N_KC);

    // ---- stage r_kc[b] slab into smem (coalesced float4) ----
    const float* rkb = r_kc + (size_t)b * (N_KC * T_TOT);
    {
        const float4* src = (const float4*)rkb;
        float4* dst = (float4*)s_rk;
        for (int i = tid; i < (N_KC * T_TOT) / 4; i += NTHREADS) dst[i] = src[i];
    }

    // ---- init small shared state ----
    if (tid < 100) {
        s_bias[tid] = bias[tid];
        float r0 = (tid < N_MBON) ? 0.0f : 0.1f;
        s_r[tid] = r0;
        out[(size_t)b * N_REC + tid] = r0;          // r_all[0]
    }
    if (tid >= 100 && tid < 108) s_r[tid] = 0.0f;   // zero pad for 16B Wr reads
    if (tid < 20)  { s_wro[tid] = W_readout[tid]; s_rbd[tid] = 0.1f; }
    if (tid < 120) s_wext[tid] = W_ext[tid];
    if (tid < 200) s_rbk[tid] = rkb[tid * T_TOT];   // rbk0 into buffer 0
    if (tid < 122) s_rext[tid] = r_ext[(size_t)b * (2 * T_TOT) + tid];
    if (tid == 0)  out[RO + b] = 0.0f;              // readout0 (MBON r is 0)

    // ---- plastic weights W / wt in registers: warp w owns rows (w, w+10) ----
    const int m1 = w;
    const int m2 = w + 10;
    float Wa[KPT], Wb_[KPT], wta[KPT], wtb[KPT];
    {
        const float* Wg  = W0  + (size_t)b * (N_MBON * N_KC);
        const float* wtg = wt0 + (size_t)b * (N_MBON * N_KC);
        #pragma unroll
        for (int i = 0; i < KPT; i++) {
            int k = lane + 32 * i;
            bool ok = (k < N_KC);
            Wa[i]  = ok ? Wg [m1 * N_KC + k] : 0.0f;
            Wb_[i] = ok ? Wg [m2 * N_KC + k] : 0.0f;
            wta[i] = ok ? wtg[m1 * N_KC + k] : 0.0f;
            wtb[i] = ok ? wtg[m2 * N_KC + k] : 0.0f;
        }
    }

    // ---- W_recur (masked -> Wm) PACKED in registers: thread-group (jj, i0) ----
    ull wm2[WM_PAIRS];
    const int jj = (tid < 300) ? (tid % 100) : 0;
    const int i0 = (tid < 300) ? (tid / 100) * WM_CHUNK : 0;
    #pragma unroll
    for (int c = 0; c < WM_PAIRS; c++) {
        int ia = i0 + 2 * c, ib = ia + 1;
        float va = 0.0f, vb = 0.0f;
        if (tid < 300 && ia < N_REC) {
            va = W_recur[jj * N_REC + ia];
            if (jj < N_MBON && ia >= N_REC - N_DAN) va = 0.0f;  // Wm mask
        }
        if (tid < 300 && ib < N_REC) {
            vb = W_recur[jj * N_REC + ib];
            if (jj < N_MBON && ib >= N_REC - N_DAN) vb = 0.0f;
        }
        wm2[c] = pk2(va, vb);
    }

    __syncthreads();

    float* out_r  = out + (size_t)B * N_REC + (size_t)b * N_REC;  // r_all[1]
    float* out_ro = out + RO + B + b;                              // readout[1]
    const size_t rstride = (size_t)B * N_REC;

    for (int t = 0; t < T_STEPS; t++) {
        const int cur = t & 1;
        const int nxt = cur ^ 1;

        // ================= P0 =================
        // rk into regs + I_kc row dots (2 independent chains)
        float rk[KPT];
        #pragma unroll
        for (int i = 0; i < KPT; i++) {
            int k = lane + 32 * i;
            rk[i] = (k < N_KC) ? s_rk[k * T_TOT + t] : 0.0f;
        }
        float p1 = 0.0f, p2 = 0.0f;
        #pragma unroll
        for (int i = 0; i < KPT; i++) {
            p1 = fmaf(Wa[i],  rk[i], p1);
            p2 = fmaf(Wb_[i], rk[i], p2);
        }
        // 3-level butterfly: lanes 0..3 hold partials over lanes == l mod 4
        #pragma unroll
        for (int o = 16; o >= 4; o >>= 1) {
            p1 += __shfl_xor_sync(0xFFFFFFFFu, p1, o);
            p2 += __shfl_xor_sync(0xFFFFFFFFu, p2, o);
        }
        if (lane < 4) {
            s_Ib[lane * 20 + m1] = p1;
            s_Ib[lane * 20 + m2] = p2;
        }

        // Wr partials: 9 x LDS.128 (as ull pairs) + 18 packed FMA2
        if (tid < 300) {
            const ulonglong2* rp = (const ulonglong2*)(s_r + i0);
            ull acc0 = 0ULL, acc1 = 0ULL;
            #pragma unroll
            for (int c = 0; c < WM_Q; c++) {
                ulonglong2 rv = rp[c];
                FMA2(acc0, wm2[2 * c],     rv.x, acc0);
                FMA2(acc1, wm2[2 * c + 1], rv.y, acc1);
            }
            float f0, f1, f2, f3;
            upk2(acc0, f0, f1);
            upk2(acc1, f2, f3);
            s_wrp[tid] = (f0 + f1) + (f2 + f3);
        }

        // rbk update: read buf[cur], write buf[nxt]
        if (tid < N_KC) {
            float rbk = s_rbk[cur * 200 + tid];
            float rkt = s_rk[tid * T_TOT + t];
            s_rbk[nxt * 200 + tid] = fmaf(rkt - rbk, cW, rbk);
        }
        __syncthreads();

        // ================= P1 (I_fbn folded in) =================
        if (tid < N_REC) {
            float x = s_wrp[tid] + s_wrp[100 + tid] + s_wrp[200 + tid]
                    + s_bias[tid];
            if (tid < N_MBON) {
                x += (s_Ib[tid] + s_Ib[20 + tid]) + (s_Ib[40 + tid] + s_Ib[60 + tid]);
            } else if (tid < N_MBON + N_FBN) {
                int q = tid - N_MBON;
                float re0 = s_rext[t];
                float re1 = s_rext[T_TOT + t];
                x += fmaf(s_wext[2 * q], re0, s_wext[2 * q + 1] * re1);
            }
            float rold = s_r[tid];
            float rn = fmaf(fmaxf(x, 0.0f) - rold, cR, rold);
            s_r[tid] = rn;
            out_r[tid] = rn;
            if (tid >= N_REC - N_DAN) {
                int d = tid - (N_REC - N_DAN);
                float rbd = s_rbd[d];
                s_rbd[d] = fmaf(rn - rbd, cW, rbd);
            }
        }
        __syncthreads();

        // ================= P2 (no trailing barrier; rbk double-buffered) ====
        {
            float rbd1d = s_rbd[m1] * dt,      rbd2d = s_rbd[m2] * dt;
            float rdn1d = -s_r[80 + m1] * dt,  rdn2d = -s_r[80 + m2] * dt;
            const float* rbk_new = s_rbk + nxt * 200;
            #pragma unroll
            for (int i = 0; i < KPT; i++) {
                int k = lane + 32 * i;
                if (k < N_KC) {
                    float rbk = rbk_new[k];
                    wta[i] = fmaf(rbd1d, rk[i], wta[i]);
                    wta[i] = fmaf(rdn1d, rbk,   wta[i]);
                    Wa[i]  = fminf(fmaxf(fmaf(wta[i] - Wa[i], cW, Wa[i]), 0.0f), 0.05f);
                    wtb[i] = fmaf(rbd2d, rk[i], wtb[i]);
                    wtb[i] = fmaf(rdn2d, rbk,   wtb[i]);
                    Wb_[i] = fminf(fmaxf(fmaf(wtb[i] - Wb_[i], cW, Wb_[i]), 0.0f), 0.05f);
                }
            }
        }

        // readout (warp 9, lightest-loaded; reads post-barrier s_r)
        if (w == 9) {
            float v = (lane < N_MBON) ? s_r[lane] * s_wro[lane] : 0.0f;
            #pragma unroll
            for (int o = 16; o > 0; o >>= 1)
                v += __shfl_xor_sync(0xFFFFFFFFu, v, o);
            if (lane == 0) *out_ro = v;
        }

        out_r  += rstride;
        out_ro += B;
        // no trailing barrier: next P0 writes s_Ib/s_wrp (readers in P1 are 1
        // barrier ahead; P2/readout don't touch them) and rbk buf[cur] (last
        // read by P0(t), 2 barriers back).
    }

    // ---- final W / wt ----
    {
        float* Wf  = out + WF  + (size_t)b * (N_MBON * N_KC);
        float* wtf = out + WTF + (size_t)b * (N_MBON * N_KC);
        #pragma unroll
        for (int i = 0; i < KPT; i++) {
            int k = lane + 32 * i;
            if (k < N_KC) {
                Wf [m1 * N_KC + k] = Wa[i];
                Wf [m2 * N_KC + k] = Wb_[i];
                wtf[m1 * N_KC + k] = wta[i];
                wtf[m2 * N_KC + k] = wtb[i];
            }
        }
    }
}

extern "C" void kernel_launch(void* const* d_in, const int* in_sizes, int n_in,
                              void* d_out, int out_size) {
    const float* r_kc      = (const float*)d_in[0];
    const float* r_ext     = (const float*)d_in[1];
    const float* timev     = (const float*)d_in[2];
    const float* W0        = (const float*)d_in[3];
    const float* wt0       = (const float*)d_in[4];
    const float* W_recur   = (const float*)d_in[5];
    const float* W_ext     = (const float*)d_in[6];
    const float* W_readout = (const float*)d_in[7];
    const float* bias      = (const float*)d_in[8];
    float* out = (float*)d_out;

    int B = in_sizes[0] / (N_KC * T_TOT);

    static bool attr_set = false;
    if (!attr_set) {
        cudaFuncSetAttribute(cond_rnn_kernel,
                             cudaFuncAttributeMaxDynamicSharedMemorySize,
                             SM_FLOATS * sizeof(float));
        attr_set = true;
    }

    cond_rnn_kernel<<<B, NTHREADS, SM_FLOATS * sizeof(float)>>>(
        r_kc, r_ext, timev, W0, wt0, W_recur, W_ext, W_readout, bias, out, B);
}